// round 11
// baseline (speedup 1.0000x reference)
#include <cuda_runtime.h>
#include <cuda_fp16.h>
#include <cstdint>

#define N_NODES 70000
#define N_EDGES 800000
#define IN_SAGE 1024
#define FEAT_CH 128
#define EXTRA 20
#define HIDDEN 37        // (128+20)/4
#define OUT_CH 3
#define FDIM 1044
#define FC1_IN 148       // FEAT_CH + EXTRA
#define NB ((N_NODES + 255) / 256)   // 274 scan blocks

// ---------------- scratch (device globals; no allocation allowed) ----------
__device__ float g_yl[(size_t)N_NODES * FEAT_CH];   // x_in @ Wl^T
__device__ float g_yr[(size_t)N_NODES * FEAT_CH];   // x_in @ Wr^T
__device__ float g_agg[(size_t)N_NODES * FEAT_CH];  // mean of yl over in-edges
__device__ __align__(16) __half g_wh[256 * IN_SAGE]; // [Wl;Wr] fp16, pair-interleaved
__device__ int g_deg[N_NODES];
__device__ int g_rowptr[N_NODES];
__device__ int g_cursor[N_NODES];
__device__ int g_csr[N_EDGES];
__device__ int g_bsum[NB];
__device__ int g_boff[NB];

// ---------------- small helpers --------------------------------------------
__device__ __forceinline__ uint32_t smem_u32(const void* p) {
    uint32_t a;
    asm("{ .reg .u64 t; cvta.to.shared.u64 t, %1; cvt.u32.u64 %0, t; }"
        : "=r"(a) : "l"(p));
    return a;
}

// pack (lo, hi) floats -> f16x2 register
__device__ __forceinline__ uint32_t pack_f16x2(float lo, float hi) {
    uint32_t d;
    asm("cvt.rn.f16x2.f32 %0, %1, %2;" : "=r"(d) : "f"(hi), "f"(lo));
    return d;
}

// mma m16n8k16 f16 x f16 -> f32 (base PTX sm_80+, no 'a' feature)
__device__ __forceinline__ void mma_f16(float* c, const uint32_t* a, const uint32_t* b) {
    asm volatile(
        "mma.sync.aligned.m16n8k16.row.col.f32.f16.f16.f32 "
        "{%0,%1,%2,%3},{%4,%5,%6,%7},{%8,%9},{%0,%1,%2,%3};"
        : "+f"(c[0]), "+f"(c[1]), "+f"(c[2]), "+f"(c[3])
        : "r"(a[0]), "r"(a[1]), "r"(a[2]), "r"(a[3]), "r"(b[0]), "r"(b[1]));
}

// ---------------- kernel: weights -> fp16, pair-interleaved ------------------
// Within each 16-k group, pairs p (k=2p,2p+1) stored at slot order
// [p0,p4,p1,p5,p2,p6,p3,p7] so fragment (p=ctg, p=ctg+4) is one LDS.64.
__global__ void prep_w_kernel(const float* __restrict__ wl, const float* __restrict__ wr) {
    int i = blockIdx.x * blockDim.x + threadIdx.x;
    if (i >= 256 * IN_SAGE) return;
    int n = i >> 10, kk = i & 1023;
    int grp = kk >> 4, within = kk & 15;
    int slot = within >> 1, h = within & 1;
    int p = (slot >> 1) + ((slot & 1) << 2);
    int srck = (grp << 4) + (p << 1) + h;
    float v = (n < 128) ? wl[n * IN_SAGE + srck] : wr[(n - 128) * IN_SAGE + srck];
    g_wh[i] = __float2half_rn(v);
}

// ---------------- kernel: zero degree ---------------------------------------
__global__ void zero_kernel() {
    int i = blockIdx.x * blockDim.x + threadIdx.x;
    if (i < N_NODES) g_deg[i] = 0;
}

// ---------------- kernel: degree histogram ----------------------------------
__global__ void hist_kernel(const int* __restrict__ edges) {
    int e = blockIdx.x * blockDim.x + threadIdx.x;
    if (e < N_EDGES) atomicAdd(&g_deg[edges[N_EDGES + e]], 1);
}

// ---------------- two-level scan --------------------------------------------
__global__ void scan1_kernel() {
    __shared__ int ws[8];
    int i = blockIdx.x * 256 + threadIdx.x;
    int v = (i < N_NODES) ? g_deg[i] : 0;
#pragma unroll
    for (int o = 16; o > 0; o >>= 1) v += __shfl_down_sync(0xffffffffu, v, o);
    if ((threadIdx.x & 31) == 0) ws[threadIdx.x >> 5] = v;
    __syncthreads();
    if (threadIdx.x == 0) {
        int s = 0;
#pragma unroll
        for (int j = 0; j < 8; j++) s += ws[j];
        g_bsum[blockIdx.x] = s;
    }
}

__global__ void scan2_kernel() {
    __shared__ int ss[512];
    int t = threadIdx.x;
    ss[t] = (t < NB) ? g_bsum[t] : 0;
    __syncthreads();
#pragma unroll
    for (int off = 1; off < 512; off <<= 1) {
        int v = (t >= off) ? ss[t - off] : 0;
        __syncthreads();
        ss[t] += v;
        __syncthreads();
    }
    if (t < NB) g_boff[t] = (t > 0) ? ss[t - 1] : 0;
}

__global__ void scan3_kernel() {
    __shared__ int ss[256];
    int t = threadIdx.x;
    int i = blockIdx.x * 256 + t;
    int d = (i < N_NODES) ? g_deg[i] : 0;
    ss[t] = d;
    __syncthreads();
#pragma unroll
    for (int off = 1; off < 256; off <<= 1) {
        int v = (t >= off) ? ss[t - off] : 0;
        __syncthreads();
        ss[t] += v;
        __syncthreads();
    }
    if (i < N_NODES) {
        int pos = g_boff[blockIdx.x] + ss[t] - d;
        g_rowptr[i] = pos;
        g_cursor[i] = pos;
    }
}

// ---------------- kernel: CSR fill -------------------------------------------
__global__ void fill_kernel(const int* __restrict__ edges) {
    int e = blockIdx.x * blockDim.x + threadIdx.x;
    if (e < N_EDGES) {
        int dst = edges[N_EDGES + e];
        int pos = atomicAdd(&g_cursor[dst], 1);
        g_csr[pos] = edges[e];
    }
}

// ---------------- kernel 2: FP16 fused dual GEMM ----------------------------
// [g_yl | g_yr][m] = X[m, :1024] @ [Wl;Wr]^T.  BM=128, BN=256, BK=32.
// 512 threads = 16 warps, warp tile 32x64 (4 warps/SMSP). fp16 m16n8k16,
// fp32 accumulate. A fp32 in smem, stride 160B (conflict-free LDS.64 float2).
// B fp16 pair-interleaved, stride 96B (conflict-free LDS.64).
#define GBM 128
#define GBK 32
#define NCH (IN_SAGE / GBK)        // 32
#define AWW 40                     // A words per row (160 B)
#define BWW 24                     // B words per row (96 B)
#define B_OFF_B (128 * 160)        // 20480 bytes
#define B_OFF_W (B_OFF_B / 4)      // 5120 words
#define STAGE_B (B_OFF_B + 256 * 96)    // 45056 bytes
#define STAGE_W (STAGE_B / 4)           // 11264 words
#define GEMM_SMEM (3 * STAGE_B)         // 135168

__device__ __forceinline__ void issue_stage(
    uint32_t sbase, const float* __restrict__ X, int m0, int k0, int tid)
{
    // A: 128 rows x 32 fp32 -> 1024 x 16B / 512 thr = 2 each
#pragma unroll
    for (int it = 0; it < 2; it++) {
        int idx = tid + it * 512;
        int row = idx >> 3, q = idx & 7;
        int m = m0 + row;
        int valid = (m < N_NODES);
        const float* src = X + (size_t)(valid ? m : 0) * FDIM + k0 + q * 4;
        asm volatile("cp.async.cg.shared.global [%0], [%1], 16, %2;"
                     :: "r"(sbase + row * 160 + q * 16), "l"(src),
                        "r"(valid ? 16 : 0));
    }
    // B: 256 rows x 32 fp16 = 64B/row -> 1024 x 16B / 512 thr = 2 each
#pragma unroll
    for (int it = 0; it < 2; it++) {
        int idx = tid + it * 512;
        int row = idx >> 2, q = idx & 3;
        const __half* src = g_wh + (size_t)row * IN_SAGE + k0 + q * 8;
        asm volatile("cp.async.cg.shared.global [%0], [%1], 16;"
                     :: "r"(sbase + B_OFF_B + row * 96 + q * 16), "l"(src));
    }
}

__global__ void __launch_bounds__(512, 1) gemm_kernel(const float* __restrict__ X) {
    extern __shared__ __align__(16) float smf[];
    const uint32_t smb = smem_u32(smf);
    const int tid = threadIdx.x;
    const int wid = tid >> 5;
    const int lane = tid & 31;
    const int gid = lane >> 2;       // 0..7
    const int ctg = lane & 3;        // 0..3
    const int warp_m = wid & 3;      // 0..3  (M32 each)
    const int warp_n = wid >> 2;     // 0..3  (N64 each)
    const int m0 = blockIdx.x * GBM;

    float acc[2][8][4];
#pragma unroll
    for (int i = 0; i < 2; i++)
#pragma unroll
        for (int j = 0; j < 8; j++)
#pragma unroll
            for (int r = 0; r < 4; r++) acc[i][j][r] = 0.0f;

    issue_stage(smb, X, m0, 0, tid);
    asm volatile("cp.async.commit_group;" ::: "memory");
    issue_stage(smb + STAGE_B, X, m0, GBK, tid);
    asm volatile("cp.async.commit_group;" ::: "memory");

    for (int c = 0; c < NCH; c++) {
        asm volatile("cp.async.wait_group 1;" ::: "memory");
        __syncthreads();
        if (c + 2 < NCH)
            issue_stage(smb + ((c + 2) % 3) * STAGE_B, X, m0, (c + 2) * GBK, tid);
        asm volatile("cp.async.commit_group;" ::: "memory");

        const float* st = smf + (c % 3) * STAGE_W;
#pragma unroll
        for (int ks = 0; ks < 2; ks++) {          // two 16-k steps per chunk
            // B fragments: one LDS.64 each -> {pair ctg, pair ctg+4}
            uint32_t b[8][2];
#pragma unroll
            for (int nt = 0; nt < 8; nt++) {
                const uint2 bv = *(const uint2*)(st + B_OFF_W +
                    (warp_n * 64 + nt * 8 + gid) * BWW + ks * 8 + 2 * ctg);
                b[nt][0] = bv.x;
                b[nt][1] = bv.y;
            }
            const int kA = ks * 16 + 2 * ctg;     // word offset of lane's k pair
#pragma unroll
            for (int mt = 0; mt < 2; mt++) {
                const float* pa = st + (warp_m * 32 + mt * 16 + gid) * AWW + kA;
                float2 v0 = *(const float2*)(pa);                  // (row,   k..k+1)
                float2 v1 = *(const float2*)(pa + 8 * AWW);        // (row+8, k..k+1)
                float2 v2 = *(const float2*)(pa + 8);              // (row,   k+8..k+9)
                float2 v3 = *(const float2*)(pa + 8 * AWW + 8);    // (row+8, k+8..k+9)
                uint32_t a[4];
                a[0] = pack_f16x2(v0.x, v0.y);
                a[1] = pack_f16x2(v1.x, v1.y);
                a[2] = pack_f16x2(v2.x, v2.y);
                a[3] = pack_f16x2(v3.x, v3.y);
#pragma unroll
                for (int nt = 0; nt < 8; nt++)
                    mma_f16(acc[mt][nt], a, b[nt]);
            }
        }
    }

#pragma unroll
    for (int mt = 0; mt < 2; mt++) {
#pragma unroll
        for (int nt = 0; nt < 8; nt++) {
            int col = warp_n * 64 + nt * 8 + 2 * ctg;       // 0..255
            float* Y = (col < 128) ? g_yl : g_yr;
            int cy = col & 127;
            int r0 = m0 + warp_m * 32 + mt * 16 + gid;
            if (r0 < N_NODES)
                *(float2*)(Y + (size_t)r0 * FEAT_CH + cy) =
                    make_float2(acc[mt][nt][0], acc[mt][nt][1]);
            int r1 = r0 + 8;
            if (r1 < N_NODES)
                *(float2*)(Y + (size_t)r1 * FEAT_CH + cy) =
                    make_float2(acc[mt][nt][2], acc[mt][nt][3]);
        }
    }
}

// ---------------- kernel 3: CSR gather (warp per node) ----------------------
__global__ __launch_bounds__(256) void gather_kernel() {
    int w = (blockIdx.x * blockDim.x + threadIdx.x) >> 5;
    int lane = threadIdx.x & 31;
    if (w >= N_NODES) return;
    int start = g_rowptr[w];
    int deg = g_deg[w];
    int end = start + deg;
    float4 acc = make_float4(0.f, 0.f, 0.f, 0.f);
    int e = start;
    for (; e + 2 <= end; e += 2) {
        int s0 = g_csr[e], s1 = g_csr[e + 1];
        float4 v0 = *(const float4*)(g_yl + (size_t)s0 * FEAT_CH + lane * 4);
        float4 v1 = *(const float4*)(g_yl + (size_t)s1 * FEAT_CH + lane * 4);
        acc.x += v0.x + v1.x; acc.y += v0.y + v1.y;
        acc.z += v0.z + v1.z; acc.w += v0.w + v1.w;
    }
    if (e < end) {
        int s0 = g_csr[e];
        float4 v0 = *(const float4*)(g_yl + (size_t)s0 * FEAT_CH + lane * 4);
        acc.x += v0.x; acc.y += v0.y; acc.z += v0.z; acc.w += v0.w;
    }
    float inv = 1.0f / (float)max(deg, 1);
    *(float4*)(g_agg + (size_t)w * FEAT_CH + lane * 4) =
        make_float4(acc.x * inv, acc.y * inv, acc.z * inv, acc.w * inv);
}

// ---------------- kernel 4: fused mean+relu+concat+fc1+bn+fc2 ---------------
__global__ __launch_bounds__(256) void final_kernel(
    const float* __restrict__ feats,
    const float* __restrict__ b_sage,
    const float* __restrict__ fc1_w, const float* __restrict__ fc1_b,
    const float* __restrict__ fc2_w, const float* __restrict__ fc2_b,
    const float* __restrict__ bn_g,  const float* __restrict__ bn_b,
    const float* __restrict__ bn_m,  const float* __restrict__ bn_v,
    float* __restrict__ out)
{
    __shared__ __align__(16) float w1s[HIDDEN * FC1_IN];
    __shared__ float vt[256][17];
    __shared__ float bss[FEAT_CH];
    __shared__ float b1[HIDDEN], sc[HIDDEN], tr[HIDDEN];
    __shared__ float w2s[OUT_CH * HIDDEN], b2[OUT_CH];

    int tid = threadIdx.x;
    int base = blockIdx.x * 256;

    for (int i = tid; i < HIDDEN * FC1_IN; i += 256) w1s[i] = fc1_w[i];
    for (int i = tid; i < FEAT_CH; i += 256) bss[i] = b_sage[i];
    for (int i = tid; i < OUT_CH * HIDDEN; i += 256) w2s[i] = fc2_w[i];
    if (tid < HIDDEN) {
        b1[tid] = fc1_b[tid];
        float s = bn_g[tid] * rsqrtf(bn_v[tid] + 1e-5f);
        sc[tid] = s;
        tr[tid] = bn_b[tid] - bn_m[tid] * s;
    }
    if (tid < OUT_CH) b2[tid] = fc2_b[tid];
    __syncthreads();

    float z[HIDDEN];
#pragma unroll
    for (int j = 0; j < HIDDEN; j++) z[j] = b1[j];

    for (int c = 0; c < 10; c++) {
        if (c < 8) {
            int i0 = c * 16;
#pragma unroll
            for (int it = 0; it < 4; it++) {
                int idx = tid + it * 256;
                int n_off = idx >> 2;
                int q = idx & 3;
                int n = base + n_off;
                float4 a = make_float4(0.f, 0.f, 0.f, 0.f);
                float4 y = make_float4(0.f, 0.f, 0.f, 0.f);
                if (n < N_NODES) {
                    a = *(const float4*)(g_agg + (size_t)n * FEAT_CH + i0 + q * 4);
                    y = *(const float4*)(g_yr  + (size_t)n * FEAT_CH + i0 + q * 4);
                }
                int ib = i0 + q * 4;
                vt[n_off][q * 4 + 0] = fmaxf(a.x + bss[ib + 0] + y.x, 0.f);
                vt[n_off][q * 4 + 1] = fmaxf(a.y + bss[ib + 1] + y.y, 0.f);
                vt[n_off][q * 4 + 2] = fmaxf(a.z + bss[ib + 2] + y.z, 0.f);
                vt[n_off][q * 4 + 3] = fmaxf(a.w + bss[ib + 3] + y.w, 0.f);
            }
        } else if (c == 8) {
#pragma unroll
            for (int it = 0; it < 4; it++) {
                int idx = tid + it * 256;
                int n_off = idx >> 2;
                int q = idx & 3;
                int n = base + n_off;
                float4 e = make_float4(0.f, 0.f, 0.f, 0.f);
                if (n < N_NODES)
                    e = *(const float4*)(feats + (size_t)n * FDIM + IN_SAGE + q * 4);
                vt[n_off][q * 4 + 0] = e.x;
                vt[n_off][q * 4 + 1] = e.y;
                vt[n_off][q * 4 + 2] = e.z;
                vt[n_off][q * 4 + 3] = e.w;
            }
        } else {
            int n = base + tid;
            float4 e = make_float4(0.f, 0.f, 0.f, 0.f);
            if (n < N_NODES)
                e = *(const float4*)(feats + (size_t)n * FDIM + IN_SAGE + 16);
            vt[tid][0] = e.x; vt[tid][1] = e.y; vt[tid][2] = e.z; vt[tid][3] = e.w;
        }
        __syncthreads();

        int i0 = (c < 9) ? c * 16 : 144;
        int ngrp = (c < 9) ? 4 : 1;
        for (int g = 0; g < ngrp; g++) {
            float v0 = vt[tid][g * 4 + 0];
            float v1 = vt[tid][g * 4 + 1];
            float v2 = vt[tid][g * 4 + 2];
            float v3 = vt[tid][g * 4 + 3];
            const float4* wp = (const float4*)(w1s + i0 + g * 4);
#pragma unroll
            for (int j = 0; j < HIDDEN; j++) {
                float4 w = wp[j * 37];
                z[j] = fmaf(w.x, v0, z[j]);
                z[j] = fmaf(w.y, v1, z[j]);
                z[j] = fmaf(w.z, v2, z[j]);
                z[j] = fmaf(w.w, v3, z[j]);
            }
        }
        __syncthreads();
    }

    int node = base + tid;
    if (node < N_NODES) {
        float h[HIDDEN];
#pragma unroll
        for (int j = 0; j < HIDDEN; j++)
            h[j] = fmaxf(z[j], 0.0f) * sc[j] + tr[j];
#pragma unroll
        for (int k = 0; k < OUT_CH; k++) {
            float s = b2[k];
#pragma unroll
            for (int j = 0; j < HIDDEN; j++)
                s = fmaf(w2s[k * HIDDEN + j], h[j], s);
            out[(size_t)node * OUT_CH + k] = s;
        }
    }
}

// ---------------- launch ----------------------------------------------------
extern "C" void kernel_launch(void* const* d_in, const int* in_sizes, int n_in,
                              void* d_out, int out_size) {
    const float* features = (const float*)d_in[0];
    const int*   edges    = (const int*)  d_in[1];
    // d_in[2] = edges2 (unused), d_in[3] = edge_features (unused)
    const float* w_sage_l = (const float*)d_in[4];
    const float* b_sage_l = (const float*)d_in[5];
    const float* w_sage_r = (const float*)d_in[6];
    const float* fc1_w    = (const float*)d_in[7];
    const float* fc1_b    = (const float*)d_in[8];
    const float* fc2_w    = (const float*)d_in[9];
    const float* fc2_b    = (const float*)d_in[10];
    const float* bn_g     = (const float*)d_in[11];
    const float* bn_b     = (const float*)d_in[12];
    const float* bn_m     = (const float*)d_in[13];
    const float* bn_v     = (const float*)d_in[14];
    float* out = (float*)d_out;

    cudaFuncSetAttribute(gemm_kernel,
                         cudaFuncAttributeMaxDynamicSharedMemorySize, GEMM_SMEM);

    // order chosen so gemm_kernel is launch #4 (the slot ncu captures)
    prep_w_kernel<<<(256 * IN_SAGE) / 256, 256>>>(w_sage_l, w_sage_r);
    zero_kernel<<<(N_NODES + 255) / 256, 256>>>();
    hist_kernel<<<(N_EDGES + 255) / 256, 256>>>(edges);

    gemm_kernel<<<(N_NODES + GBM - 1) / GBM, 512, GEMM_SMEM>>>(features);

    scan1_kernel<<<NB, 256>>>();
    scan2_kernel<<<1, 512>>>();
    scan3_kernel<<<NB, 256>>>();
    fill_kernel<<<(N_EDGES + 255) / 256, 256>>>(edges);

    gather_kernel<<<(N_NODES * 32 + 255) / 256, 256>>>();

    final_kernel<<<(N_NODES + 255) / 256, 256>>>(
        features, b_sage_l, fc1_w, fc1_b, fc2_w, fc2_b,
        bn_g, bn_b, bn_m, bn_v, out);
}

// round 12
// speedup vs baseline: 1.1514x; 1.1514x over previous
#include <cuda_runtime.h>
#include <cuda_fp16.h>
#include <cstdint>

#define N_NODES 70000
#define N_EDGES 800000
#define IN_SAGE 1024
#define FEAT_CH 128
#define EXTRA 20
#define HIDDEN 37        // (128+20)/4
#define OUT_CH 3
#define FDIM 1044
#define FC1_IN 148       // FEAT_CH + EXTRA
#define NB ((N_NODES + 255) / 256)   // 274 scan blocks

// ---------------- scratch (device globals; no allocation allowed) ----------
__device__ __align__(16) __half g_ylh[(size_t)N_NODES * FEAT_CH]; // x@Wl^T (fp16)
__device__ float g_yr[(size_t)N_NODES * FEAT_CH];   // x_in @ Wr^T
__device__ float g_agg[(size_t)N_NODES * FEAT_CH];  // mean of yl over in-edges
__device__ __align__(16) __half g_wh[256 * IN_SAGE]; // [Wl;Wr] fp16, pair-interleaved
__device__ int g_deg[N_NODES];
__device__ int g_rowptr[N_NODES];
__device__ int g_cursor[N_NODES];
__device__ int g_csr[N_EDGES];
__device__ int g_bsum[NB];
__device__ int g_boff[NB];

// ---------------- small helpers --------------------------------------------
__device__ __forceinline__ uint32_t smem_u32(const void* p) {
    uint32_t a;
    asm("{ .reg .u64 t; cvta.to.shared.u64 t, %1; cvt.u32.u64 %0, t; }"
        : "=r"(a) : "l"(p));
    return a;
}

// pack (lo, hi) floats -> f16x2 register
__device__ __forceinline__ uint32_t pack_f16x2(float lo, float hi) {
    uint32_t d;
    asm("cvt.rn.f16x2.f32 %0, %1, %2;" : "=r"(d) : "f"(hi), "f"(lo));
    return d;
}

// mma m16n8k16 f16 x f16 -> f32 (base PTX sm_80+, no 'a' feature)
__device__ __forceinline__ void mma_f16(float* c, const uint32_t* a, const uint32_t* b) {
    asm volatile(
        "mma.sync.aligned.m16n8k16.row.col.f32.f16.f16.f32 "
        "{%0,%1,%2,%3},{%4,%5,%6,%7},{%8,%9},{%0,%1,%2,%3};"
        : "+f"(c[0]), "+f"(c[1]), "+f"(c[2]), "+f"(c[3])
        : "r"(a[0]), "r"(a[1]), "r"(a[2]), "r"(a[3]), "r"(b[0]), "r"(b[1]));
}

// ---------------- kernel: weights -> fp16, pair-interleaved ------------------
__global__ void prep_w_kernel(const float* __restrict__ wl, const float* __restrict__ wr) {
    int i = blockIdx.x * blockDim.x + threadIdx.x;
    if (i >= 256 * IN_SAGE) return;
    int n = i >> 10, kk = i & 1023;
    int grp = kk >> 4, within = kk & 15;
    int slot = within >> 1, h = within & 1;
    int p = (slot >> 1) + ((slot & 1) << 2);
    int srck = (grp << 4) + (p << 1) + h;
    float v = (n < 128) ? wl[n * IN_SAGE + srck] : wr[(n - 128) * IN_SAGE + srck];
    g_wh[i] = __float2half_rn(v);
}

// ---------------- CSR build chain -------------------------------------------
__global__ void zero_kernel() {
    int i = blockIdx.x * blockDim.x + threadIdx.x;
    if (i < N_NODES) g_deg[i] = 0;
}

__global__ void hist_kernel(const int* __restrict__ edges) {
    int e = blockIdx.x * blockDim.x + threadIdx.x;
    if (e < N_EDGES) atomicAdd(&g_deg[edges[N_EDGES + e]], 1);
}

__global__ void scan1_kernel() {
    __shared__ int ws[8];
    int i = blockIdx.x * 256 + threadIdx.x;
    int v = (i < N_NODES) ? g_deg[i] : 0;
#pragma unroll
    for (int o = 16; o > 0; o >>= 1) v += __shfl_down_sync(0xffffffffu, v, o);
    if ((threadIdx.x & 31) == 0) ws[threadIdx.x >> 5] = v;
    __syncthreads();
    if (threadIdx.x == 0) {
        int s = 0;
#pragma unroll
        for (int j = 0; j < 8; j++) s += ws[j];
        g_bsum[blockIdx.x] = s;
    }
}

__global__ void scan2_kernel() {
    __shared__ int ss[512];
    int t = threadIdx.x;
    ss[t] = (t < NB) ? g_bsum[t] : 0;
    __syncthreads();
#pragma unroll
    for (int off = 1; off < 512; off <<= 1) {
        int v = (t >= off) ? ss[t - off] : 0;
        __syncthreads();
        ss[t] += v;
        __syncthreads();
    }
    if (t < NB) g_boff[t] = (t > 0) ? ss[t - 1] : 0;
}

__global__ void scan3_kernel() {
    __shared__ int ss[256];
    int t = threadIdx.x;
    int i = blockIdx.x * 256 + t;
    int d = (i < N_NODES) ? g_deg[i] : 0;
    ss[t] = d;
    __syncthreads();
#pragma unroll
    for (int off = 1; off < 256; off <<= 1) {
        int v = (t >= off) ? ss[t - off] : 0;
        __syncthreads();
        ss[t] += v;
        __syncthreads();
    }
    if (i < N_NODES) {
        int pos = g_boff[blockIdx.x] + ss[t] - d;
        g_rowptr[i] = pos;
        g_cursor[i] = pos;
    }
}

__global__ void fill_kernel(const int* __restrict__ edges) {
    int e = blockIdx.x * blockDim.x + threadIdx.x;
    if (e < N_EDGES) {
        int dst = edges[N_EDGES + e];
        int pos = atomicAdd(&g_cursor[dst], 1);
        g_csr[pos] = edges[e];
    }
}

// ---------------- kernel 2: FP16 fused dual GEMM ----------------------------
// y_l stored fp16 (gather-only consumer), y_r fp32. 256 thr, warp tile 64x64.
#define GBM 128
#define GBK 32
#define NCH (IN_SAGE / GBK)        // 32
#define AWW 40                     // A words per row (160 B)
#define BWW 24                     // B words per row (96 B)
#define B_OFF_B (128 * 160)        // 20480 bytes
#define B_OFF_W (B_OFF_B / 4)      // 5120 words
#define STAGE_B (B_OFF_B + 256 * 96)    // 45056 bytes
#define STAGE_W (STAGE_B / 4)           // 11264 words
#define GEMM_SMEM (3 * STAGE_B)         // 135168

__device__ __forceinline__ void issue_stage(
    uint32_t sbase, const float* __restrict__ X, int m0, int k0, int tid)
{
#pragma unroll
    for (int it = 0; it < 4; it++) {
        int idx = tid + it * 256;
        int row = idx >> 3, q = idx & 7;
        int m = m0 + row;
        int valid = (m < N_NODES);
        const float* src = X + (size_t)(valid ? m : 0) * FDIM + k0 + q * 4;
        asm volatile("cp.async.cg.shared.global [%0], [%1], 16, %2;"
                     :: "r"(sbase + row * 160 + q * 16), "l"(src),
                        "r"(valid ? 16 : 0));
    }
#pragma unroll
    for (int it = 0; it < 4; it++) {
        int idx = tid + it * 256;
        int row = idx >> 2, q = idx & 3;
        const __half* src = g_wh + (size_t)row * IN_SAGE + k0 + q * 8;
        asm volatile("cp.async.cg.shared.global [%0], [%1], 16;"
                     :: "r"(sbase + B_OFF_B + row * 96 + q * 16), "l"(src));
    }
}

__global__ void __launch_bounds__(256, 1) gemm_kernel(const float* __restrict__ X) {
    extern __shared__ __align__(16) float smf[];
    const uint32_t smb = smem_u32(smf);
    const int tid = threadIdx.x;
    const int wid = tid >> 5;
    const int lane = tid & 31;
    const int gid = lane >> 2;
    const int ctg = lane & 3;
    const int warp_m = wid >> 2;     // 0..1  (M64)
    const int warp_n = wid & 3;      // 0..3  (N64)
    const int m0 = blockIdx.x * GBM;

    float acc[4][8][4];
#pragma unroll
    for (int i = 0; i < 4; i++)
#pragma unroll
        for (int j = 0; j < 8; j++)
#pragma unroll
            for (int r = 0; r < 4; r++) acc[i][j][r] = 0.0f;

    issue_stage(smb, X, m0, 0, tid);
    asm volatile("cp.async.commit_group;" ::: "memory");
    issue_stage(smb + STAGE_B, X, m0, GBK, tid);
    asm volatile("cp.async.commit_group;" ::: "memory");

    for (int c = 0; c < NCH; c++) {
        asm volatile("cp.async.wait_group 1;" ::: "memory");
        __syncthreads();
        if (c + 2 < NCH)
            issue_stage(smb + ((c + 2) % 3) * STAGE_B, X, m0, (c + 2) * GBK, tid);
        asm volatile("cp.async.commit_group;" ::: "memory");

        const float* st = smf + (c % 3) * STAGE_W;
#pragma unroll
        for (int ks = 0; ks < 2; ks++) {
            uint32_t b[8][2];
#pragma unroll
            for (int nt = 0; nt < 8; nt++) {
                const uint2 bv = *(const uint2*)(st + B_OFF_W +
                    (warp_n * 64 + nt * 8 + gid) * BWW + ks * 8 + 2 * ctg);
                b[nt][0] = bv.x;
                b[nt][1] = bv.y;
            }
            const int kA = ks * 16 + 2 * ctg;
#pragma unroll
            for (int mt = 0; mt < 4; mt++) {
                const float* pa = st + (warp_m * 64 + mt * 16 + gid) * AWW + kA;
                float2 v0 = *(const float2*)(pa);
                float2 v1 = *(const float2*)(pa + 8 * AWW);
                float2 v2 = *(const float2*)(pa + 8);
                float2 v3 = *(const float2*)(pa + 8 * AWW + 8);
                uint32_t a[4];
                a[0] = pack_f16x2(v0.x, v0.y);
                a[1] = pack_f16x2(v1.x, v1.y);
                a[2] = pack_f16x2(v2.x, v2.y);
                a[3] = pack_f16x2(v3.x, v3.y);
#pragma unroll
                for (int nt = 0; nt < 8; nt++)
                    mma_f16(acc[mt][nt], a, b[nt]);
            }
        }
    }

#pragma unroll
    for (int mt = 0; mt < 4; mt++) {
#pragma unroll
        for (int nt = 0; nt < 8; nt++) {
            int col = warp_n * 64 + nt * 8 + 2 * ctg;       // 0..255
            int r0 = m0 + warp_m * 64 + mt * 16 + gid;
            int r1 = r0 + 8;
            if (col < 128) {
                // y_l in fp16 (pairs of adjacent cols -> one 4B store)
                if (r0 < N_NODES)
                    *(uint32_t*)(g_ylh + (size_t)r0 * FEAT_CH + col) =
                        pack_f16x2(acc[mt][nt][0], acc[mt][nt][1]);
                if (r1 < N_NODES)
                    *(uint32_t*)(g_ylh + (size_t)r1 * FEAT_CH + col) =
                        pack_f16x2(acc[mt][nt][2], acc[mt][nt][3]);
            } else {
                int cy = col - 128;
                if (r0 < N_NODES)
                    *(float2*)(g_yr + (size_t)r0 * FEAT_CH + cy) =
                        make_float2(acc[mt][nt][0], acc[mt][nt][1]);
                if (r1 < N_NODES)
                    *(float2*)(g_yr + (size_t)r1 * FEAT_CH + cy) =
                        make_float2(acc[mt][nt][2], acc[mt][nt][3]);
            }
        }
    }
}

// ---------------- kernel 3: CSR gather (warp per node, fp16 rows) ------------
__global__ __launch_bounds__(256) void gather_kernel() {
    int w = (blockIdx.x * blockDim.x + threadIdx.x) >> 5;
    int lane = threadIdx.x & 31;
    if (w >= N_NODES) return;
    int start = g_rowptr[w];
    int deg = g_deg[w];
    int end = start + deg;
    float4 acc = make_float4(0.f, 0.f, 0.f, 0.f);
    for (int e = start; e < end; e++) {
        int s0 = g_csr[e];
        uint2 u = *(const uint2*)(g_ylh + (size_t)s0 * FEAT_CH + lane * 4);
        __half2 h0 = *reinterpret_cast<__half2*>(&u.x);
        __half2 h1 = *reinterpret_cast<__half2*>(&u.y);
        float2 f0 = __half22float2(h0);
        float2 f1 = __half22float2(h1);
        acc.x += f0.x; acc.y += f0.y; acc.z += f1.x; acc.w += f1.y;
    }
    float inv = 1.0f / (float)max(deg, 1);
    *(float4*)(g_agg + (size_t)w * FEAT_CH + lane * 4) =
        make_float4(acc.x * inv, acc.y * inv, acc.z * inv, acc.w * inv);
}

// ---------------- kernel 4: fused mean+relu+concat+fc1+bn+fc2 ---------------
__global__ __launch_bounds__(256) void final_kernel(
    const float* __restrict__ feats,
    const float* __restrict__ b_sage,
    const float* __restrict__ fc1_w, const float* __restrict__ fc1_b,
    const float* __restrict__ fc2_w, const float* __restrict__ fc2_b,
    const float* __restrict__ bn_g,  const float* __restrict__ bn_b,
    const float* __restrict__ bn_m,  const float* __restrict__ bn_v,
    float* __restrict__ out)
{
    __shared__ __align__(16) float w1s[HIDDEN * FC1_IN];
    __shared__ float vt[256][17];
    __shared__ float bss[FEAT_CH];
    __shared__ float b1[HIDDEN], sc[HIDDEN], tr[HIDDEN];
    __shared__ float w2s[OUT_CH * HIDDEN], b2[OUT_CH];

    int tid = threadIdx.x;
    int base = blockIdx.x * 256;

    for (int i = tid; i < HIDDEN * FC1_IN; i += 256) w1s[i] = fc1_w[i];
    for (int i = tid; i < FEAT_CH; i += 256) bss[i] = b_sage[i];
    for (int i = tid; i < OUT_CH * HIDDEN; i += 256) w2s[i] = fc2_w[i];
    if (tid < HIDDEN) {
        b1[tid] = fc1_b[tid];
        float s = bn_g[tid] * rsqrtf(bn_v[tid] + 1e-5f);
        sc[tid] = s;
        tr[tid] = bn_b[tid] - bn_m[tid] * s;
    }
    if (tid < OUT_CH) b2[tid] = fc2_b[tid];
    __syncthreads();

    float z[HIDDEN];
#pragma unroll
    for (int j = 0; j < HIDDEN; j++) z[j] = b1[j];

    for (int c = 0; c < 10; c++) {
        if (c < 8) {
            int i0 = c * 16;
#pragma unroll
            for (int it = 0; it < 4; it++) {
                int idx = tid + it * 256;
                int n_off = idx >> 2;
                int q = idx & 3;
                int n = base + n_off;
                float4 a = make_float4(0.f, 0.f, 0.f, 0.f);
                float4 y = make_float4(0.f, 0.f, 0.f, 0.f);
                if (n < N_NODES) {
                    a = *(const float4*)(g_agg + (size_t)n * FEAT_CH + i0 + q * 4);
                    y = *(const float4*)(g_yr  + (size_t)n * FEAT_CH + i0 + q * 4);
                }
                int ib = i0 + q * 4;
                vt[n_off][q * 4 + 0] = fmaxf(a.x + bss[ib + 0] + y.x, 0.f);
                vt[n_off][q * 4 + 1] = fmaxf(a.y + bss[ib + 1] + y.y, 0.f);
                vt[n_off][q * 4 + 2] = fmaxf(a.z + bss[ib + 2] + y.z, 0.f);
                vt[n_off][q * 4 + 3] = fmaxf(a.w + bss[ib + 3] + y.w, 0.f);
            }
        } else if (c == 8) {
#pragma unroll
            for (int it = 0; it < 4; it++) {
                int idx = tid + it * 256;
                int n_off = idx >> 2;
                int q = idx & 3;
                int n = base + n_off;
                float4 e = make_float4(0.f, 0.f, 0.f, 0.f);
                if (n < N_NODES)
                    e = *(const float4*)(feats + (size_t)n * FDIM + IN_SAGE + q * 4);
                vt[n_off][q * 4 + 0] = e.x;
                vt[n_off][q * 4 + 1] = e.y;
                vt[n_off][q * 4 + 2] = e.z;
                vt[n_off][q * 4 + 3] = e.w;
            }
        } else {
            int n = base + tid;
            float4 e = make_float4(0.f, 0.f, 0.f, 0.f);
            if (n < N_NODES)
                e = *(const float4*)(feats + (size_t)n * FDIM + IN_SAGE + 16);
            vt[tid][0] = e.x; vt[tid][1] = e.y; vt[tid][2] = e.z; vt[tid][3] = e.w;
        }
        __syncthreads();

        int i0 = (c < 9) ? c * 16 : 144;
        int ngrp = (c < 9) ? 4 : 1;
        for (int g = 0; g < ngrp; g++) {
            float v0 = vt[tid][g * 4 + 0];
            float v1 = vt[tid][g * 4 + 1];
            float v2 = vt[tid][g * 4 + 2];
            float v3 = vt[tid][g * 4 + 3];
            const float4* wp = (const float4*)(w1s + i0 + g * 4);
#pragma unroll
            for (int j = 0; j < HIDDEN; j++) {
                float4 w = wp[j * 37];
                z[j] = fmaf(w.x, v0, z[j]);
                z[j] = fmaf(w.y, v1, z[j]);
                z[j] = fmaf(w.z, v2, z[j]);
                z[j] = fmaf(w.w, v3, z[j]);
            }
        }
        __syncthreads();
    }

    int node = base + tid;
    if (node < N_NODES) {
        float h[HIDDEN];
#pragma unroll
        for (int j = 0; j < HIDDEN; j++)
            h[j] = fmaxf(z[j], 0.0f) * sc[j] + tr[j];
#pragma unroll
        for (int k = 0; k < OUT_CH; k++) {
            float s = b2[k];
#pragma unroll
            for (int j = 0; j < HIDDEN; j++)
                s = fmaf(w2s[k * HIDDEN + j], h[j], s);
            out[(size_t)node * OUT_CH + k] = s;
        }
    }
}

// ---------------- launch ----------------------------------------------------
extern "C" void kernel_launch(void* const* d_in, const int* in_sizes, int n_in,
                              void* d_out, int out_size) {
    const float* features = (const float*)d_in[0];
    const int*   edges    = (const int*)  d_in[1];
    // d_in[2] = edges2 (unused), d_in[3] = edge_features (unused)
    const float* w_sage_l = (const float*)d_in[4];
    const float* b_sage_l = (const float*)d_in[5];
    const float* w_sage_r = (const float*)d_in[6];
    const float* fc1_w    = (const float*)d_in[7];
    const float* fc1_b    = (const float*)d_in[8];
    const float* fc2_w    = (const float*)d_in[9];
    const float* fc2_b    = (const float*)d_in[10];
    const float* bn_g     = (const float*)d_in[11];
    const float* bn_b     = (const float*)d_in[12];
    const float* bn_m     = (const float*)d_in[13];
    const float* bn_v     = (const float*)d_in[14];
    float* out = (float*)d_out;

    // persistent side stream + events (created once; no device memory involved)
    static cudaStream_t s1 = nullptr;
    static cudaEvent_t evFork = nullptr, evCSR = nullptr;
    if (s1 == nullptr) {
        cudaStreamCreateWithFlags(&s1, cudaStreamNonBlocking);
        cudaEventCreateWithFlags(&evFork, cudaEventDisableTiming);
        cudaEventCreateWithFlags(&evCSR, cudaEventDisableTiming);
    }

    cudaFuncSetAttribute(gemm_kernel,
                         cudaFuncAttributeMaxDynamicSharedMemorySize, GEMM_SMEM);

    // fork: CSR build on s1, GEMM on default stream
    cudaEventRecord(evFork, 0);
    cudaStreamWaitEvent(s1, evFork, 0);

    zero_kernel<<<(N_NODES + 255) / 256, 256, 0, s1>>>();
    hist_kernel<<<(N_EDGES + 255) / 256, 256, 0, s1>>>(edges);
    scan1_kernel<<<NB, 256, 0, s1>>>();
    scan2_kernel<<<1, 512, 0, s1>>>();
    scan3_kernel<<<NB, 256, 0, s1>>>();
    fill_kernel<<<(N_EDGES + 255) / 256, 256, 0, s1>>>(edges);
    cudaEventRecord(evCSR, s1);

    prep_w_kernel<<<(256 * IN_SAGE) / 256, 256>>>(w_sage_l, w_sage_r);
    gemm_kernel<<<(N_NODES + GBM - 1) / GBM, 256, GEMM_SMEM>>>(features);

    // join: gather needs CSR + g_ylh
    cudaStreamWaitEvent(0, evCSR, 0);

    gather_kernel<<<(N_NODES * 32 + 255) / 256, 256>>>();

    final_kernel<<<(N_NODES + 255) / 256, 256>>>(
        features, b_sage_l, fc1_w, fc1_b, fc2_w, fc2_b,
        bn_g, bn_b, bn_m, bn_v, out);
}